// round 12
// baseline (speedup 1.0000x reference)
#include <cuda_runtime.h>
#include <cstdint>

#define B_ 64
#define T_ 128
#define E_ 512
#define U_ 1024
#define G_ 3072          // 3*U
#define SGST 68          // sG row stride (floats)
#define HID_OFF (B_*T_*U_)

typedef unsigned long long ull;

// ---------------- device scratch (static, allocation-free) ----------------
__device__ __align__(256) float d_XT[T_][E_][B_];       // emb(tokens), [t_orig][e][b]
__device__ __align__(256) float d_xg[2][T_][G_][B_];    // input projections per scan step
__device__ __align__(256) float d_hT[2][T_][B_][U_];    // hidden chain, TRANSPOSED [b][u]
__device__ __align__(256) float d_h0[U_][B_];           // zeros (used as flat zero block)
__device__ unsigned g_bar;                              // monotonic grid barrier

// ---------------- f32x2 helpers ----------------
__device__ __forceinline__ ull pk2(float v) {
    ull r; asm("mov.b64 %0, {%1, %1};" : "=l"(r) : "f"(v)); return r;
}
__device__ __forceinline__ ull mk2(float lo, float hi) {
    ull r; asm("mov.b64 %0, {%1, %2};" : "=l"(r) : "f"(lo), "f"(hi)); return r;
}
__device__ __forceinline__ void unpk2(ull v, float& lo, float& hi) {
    asm("mov.b64 {%0, %1}, %2;" : "=f"(lo), "=f"(hi) : "l"(v));
}
__device__ __forceinline__ void fma2(ull& d, ull a, ull b) {
    asm("fma.rn.f32x2 %0, %1, %2, %0;" : "+l"(d) : "l"(a), "l"(b));
}
__device__ __forceinline__ ull add2(ull a, ull b) {
    ull r; asm("add.rn.f32x2 %0, %1, %2;" : "=l"(r) : "l"(a), "l"(b)); return r;
}
__device__ __forceinline__ float sigf(float x) { return 1.0f / (1.0f + __expf(-x)); }

union F4 { float4 v; float f[4]; ull u[2]; };
union F2 { float2 v; float f[2]; };

// ---------------- init ----------------
__global__ void k_init() {
    int n = U_ * B_;
    float* p = &d_h0[0][0];
    for (int i = blockIdx.x * blockDim.x + threadIdx.x; i < n; i += gridDim.x * blockDim.x)
        p[i] = 0.0f;
    if (blockIdx.x == 0 && threadIdx.x == 0) g_bar = 0u;
}

// ---------------- embedding gather ----------------
__global__ void k_embed(const int* __restrict__ tokens, const float* __restrict__ emb) {
    int t = blockIdx.x;
    int b = threadIdx.x & 63;
    int sub = threadIdx.x >> 6;
    int tok = tokens[b * T_ + t];
    const float* er = emb + (size_t)tok * E_;
    for (int e = sub; e < E_; e += 4)
        d_XT[t][e][b] = er[e];
}

// ---------------- input projection GEMM (unchanged, passing) ----------------
__global__ void __launch_bounds__(128) k_gemm_in(const float* __restrict__ Wf,
                                                 const float* __restrict__ Wb,
                                                 const float* __restrict__ bif,
                                                 const float* __restrict__ bib) {
    int gt = blockIdx.x, s = blockIdx.y, dir = blockIdx.z;
    int g0 = gt * 48;
    int torig = dir ? s : (T_ - 1 - s);
    const float* W  = dir ? Wb  : Wf;
    const float* bi = dir ? bib : bif;

    __shared__ __align__(16) float sW[64 * 48];
    __shared__ __align__(16) float sA[64 * 64];

    int tid = threadIdx.x;
    int kh = tid >> 6, r = tid & 63, cg = r >> 3, bg = r & 7;
    int b0 = bg << 3, c0 = cg * 6;

    ull acc[6][4];
#pragma unroll
    for (int j = 0; j < 6; j++) {
        ull init = kh ? 0ull : pk2(bi[g0 + c0 + j]);
#pragma unroll
        for (int p = 0; p < 4; p++) acc[j][p] = init;
    }

    for (int kc = 0; kc < E_ / 64; kc++) {
        __syncthreads();
        for (int idx = tid; idx < 64 * 48; idx += 128) {
            int kk = idx / 48, c = idx - kk * 48;
            sW[idx] = W[(size_t)(kc * 64 + kk) * G_ + g0 + c];
        }
        const float4* src = (const float4*)(&d_XT[torig][kc * 64][0]);
        float4* dst = (float4*)sA;
#pragma unroll
        for (int i = 0; i < 8; i++) dst[tid + i * 128] = src[tid + i * 128];
        __syncthreads();

        const float* hb  = sA + (kh * 32) * 64;
        const float* wb_ = sW + (kh * 32) * 48;
#pragma unroll 4
        for (int kk = 0; kk < 32; kk++) {
            ull hp[4];
#pragma unroll
            for (int p = 0; p < 4; p++) hp[p] = *(const ull*)(hb + kk * 64 + b0 + 2 * p);
#pragma unroll
            for (int j = 0; j < 6; j++) {
                ull us = pk2(wb_[kk * 48 + c0 + j]);
#pragma unroll
                for (int p = 0; p < 4; p++) fma2(acc[j][p], hp[p], us);
            }
        }
    }
    __syncthreads();
    ull* part = (ull*)sA;
    if (kh) {
#pragma unroll
        for (int j = 0; j < 6; j++)
#pragma unroll
            for (int p = 0; p < 4; p++) part[r * 24 + j * 4 + p] = acc[j][p];
    }
    __syncthreads();
    if (!kh) {
#pragma unroll
        for (int j = 0; j < 6; j++) {
#pragma unroll
            for (int q = 0; q < 2; q++) {
                F4 o;
                o.u[0] = add2(acc[j][2 * q + 0], part[r * 24 + j * 4 + 2 * q + 0]);
                o.u[1] = add2(acc[j][2 * q + 1], part[r * 24 + j * 4 + 2 * q + 1]);
                *(float4*)(&d_xg[dir][s][g0 + c0 + j][b0 + 4 * q]) = o.v;
            }
        }
    }
}

// ---------------- persistent recurrent kernel ----------------
// R12: k-parity f32x2 lanes. Weights smem-resident as [kp][c][2] (3x aligned
// conflict-free LDS.128 per kp, halves ARE the k-pairs). h read from L2 as
// d_hT[dir][s-1][b][k] (k contiguous; LDG.128 = 2 h-pairs). Zero packing MOVs.
// acc[6c][4b] with k-parity lanes, collapsed lo+hi at step end.
__global__ void __launch_bounds__(512, 1) k_rec(const float* __restrict__ Uf,
                                                const float* __restrict__ Ub,
                                                const float* __restrict__ bhf,
                                                const float* __restrict__ bhb) {
    extern __shared__ __align__(16) float smem[];
    float* sU = smem;                // 48*1024 floats = 196608 B, layout [kp][c][2]
    float* sS = smem + 48 * 1024;    // 8192 floats scratch: P0 [0,3072), sG [3072,6336), sHN [6336,7424)

    int dir = blockIdx.x >> 6;
    int uc  = blockIdx.x & 63;
    int u0  = uc << 4;
    const float* Uw = dir ? Ub : Uf;
    const float* bh = dir ? bhb : bhf;
    int tid = threadIdx.x;
    unsigned nCTA = gridDim.x;

    // one-time: Uw slice -> sU[kp][c][2]; element (k,c) at kp*96 + c*2 + (k&1)
    for (int idx = tid; idx < 48 * 1024; idx += 512) {
        int kp = idx / 96, rem = idx - kp * 96;
        int c = rem >> 1, kb = rem & 1;
        int k = 2 * kp + kb;
        sU[idx] = Uw[(size_t)k * G_ + (c >> 4) * U_ + u0 + (c & 15)];
    }

    int kh = tid >> 7;                 // 0..3: k quarter [kh*256, kh*256+256)
    int r  = tid & 127;
    int cg = r & 7, bg = r >> 3;       // 8 cgs, 16 bgs
    int c0 = cg * 6, b0 = bg * 4;

    // bias (kh0 only): acc lanes (bias, 0) so lo+hi collapse adds it once
    ull binit[6];
#pragma unroll
    for (int j = 0; j < 6; j++) {
        if (kh) { binit[j] = 0ull; continue; }
        int c = c0 + j;
        binit[j] = mk2(bh[(c >> 4) * U_ + u0 + (c & 15)], 0.0f);
    }

    // epilogue mapping A (compute): (u=eu, b pair eb)
    int eu = tid >> 5;                 // 0..15
    int eb = (tid & 31) * 2;           // 0..62
    int gu = u0 + eu;
    // epilogue mapping B (transposed write): (b=b2, u pair up)
    int up = (tid & 7) * 2;            // 0..14
    int b2 = tid >> 3;                 // 0..63
    const float* xgbase = &d_xg[dir][0][0][0];

    const float* ubB = sU + (size_t)(kh * 128) * 96 + c0 * 2;  // this thread's weight base

    __syncthreads();                   // sU resident

    for (int s = 0; s < T_; s++) {
        const float* hT = (s == 0) ? &d_h0[0][0] : &d_hT[dir][s - 1][0][0];

        // h row pointers for the 4 b's; k window [kh*256, kh*256+256)
        const float* hr0 = hT + (size_t)(b0 + 0) * U_ + kh * 256;
        const float* hr1 = hT + (size_t)(b0 + 1) * U_ + kh * 256;
        const float* hr2 = hT + (size_t)(b0 + 2) * U_ + kh * 256;
        const float* hr3 = hT + (size_t)(b0 + 3) * U_ + kh * 256;

        // prefetch h_prev for epilogue (2 scalar ldcg; 2 regs held)
        F2 hpv;
        hpv.f[0] = __ldcg(hT + (size_t)eb * U_ + gu);
        hpv.f[1] = __ldcg(hT + (size_t)(eb + 1) * U_ + gu);

        ull acc[6][4];
#pragma unroll
        for (int j = 0; j < 6; j++)
#pragma unroll
            for (int b = 0; b < 4; b++) acc[j][b] = binit[j];

        // mainloop: 64 groups of 4 k rows; 1-group LDG lookahead; zero barriers
        F4 ha0, ha1, ha2, ha3;
        ha0.v = __ldcg((const float4*)hr0);
        ha1.v = __ldcg((const float4*)hr1);
        ha2.v = __ldcg((const float4*)hr2);
        ha3.v = __ldcg((const float4*)hr3);
#pragma unroll 1
        for (int g = 0; g < 64; g++) {
            F4 hb0_, hb1_, hb2_, hb3_;
            int gn = (g < 63) ? (g + 1) : 63;
            hb0_.v = __ldcg((const float4*)(hr0 + gn * 4));
            hb1_.v = __ldcg((const float4*)(hr1 + gn * 4));
            hb2_.v = __ldcg((const float4*)(hr2 + gn * 4));
            hb3_.v = __ldcg((const float4*)(hr3 + gn * 4));

            const float* wp = ubB + (size_t)g * 192;   // 2 kp rows of 96
            F4 qa0, qb0, qc0, qa1, qb1, qc1;
            qa0.v = *(const float4*)(wp);
            qb0.v = *(const float4*)(wp + 4);
            qc0.v = *(const float4*)(wp + 8);
            qa1.v = *(const float4*)(wp + 96);
            qb1.v = *(const float4*)(wp + 100);
            qc1.v = *(const float4*)(wp + 104);

            // kp0: h pairs = ha*.u[0]
            fma2(acc[0][0], ha0.u[0], qa0.u[0]); fma2(acc[0][1], ha1.u[0], qa0.u[0]);
            fma2(acc[0][2], ha2.u[0], qa0.u[0]); fma2(acc[0][3], ha3.u[0], qa0.u[0]);
            fma2(acc[1][0], ha0.u[0], qa0.u[1]); fma2(acc[1][1], ha1.u[0], qa0.u[1]);
            fma2(acc[1][2], ha2.u[0], qa0.u[1]); fma2(acc[1][3], ha3.u[0], qa0.u[1]);
            fma2(acc[2][0], ha0.u[0], qb0.u[0]); fma2(acc[2][1], ha1.u[0], qb0.u[0]);
            fma2(acc[2][2], ha2.u[0], qb0.u[0]); fma2(acc[2][3], ha3.u[0], qb0.u[0]);
            fma2(acc[3][0], ha0.u[0], qb0.u[1]); fma2(acc[3][1], ha1.u[0], qb0.u[1]);
            fma2(acc[3][2], ha2.u[0], qb0.u[1]); fma2(acc[3][3], ha3.u[0], qb0.u[1]);
            fma2(acc[4][0], ha0.u[0], qc0.u[0]); fma2(acc[4][1], ha1.u[0], qc0.u[0]);
            fma2(acc[4][2], ha2.u[0], qc0.u[0]); fma2(acc[4][3], ha3.u[0], qc0.u[0]);
            fma2(acc[5][0], ha0.u[0], qc0.u[1]); fma2(acc[5][1], ha1.u[0], qc0.u[1]);
            fma2(acc[5][2], ha2.u[0], qc0.u[1]); fma2(acc[5][3], ha3.u[0], qc0.u[1]);
            // kp1: h pairs = ha*.u[1]
            fma2(acc[0][0], ha0.u[1], qa1.u[0]); fma2(acc[0][1], ha1.u[1], qa1.u[0]);
            fma2(acc[0][2], ha2.u[1], qa1.u[0]); fma2(acc[0][3], ha3.u[1], qa1.u[0]);
            fma2(acc[1][0], ha0.u[1], qa1.u[1]); fma2(acc[1][1], ha1.u[1], qa1.u[1]);
            fma2(acc[1][2], ha2.u[1], qa1.u[1]); fma2(acc[1][3], ha3.u[1], qa1.u[1]);
            fma2(acc[2][0], ha0.u[1], qb1.u[0]); fma2(acc[2][1], ha1.u[1], qb1.u[0]);
            fma2(acc[2][2], ha2.u[1], qb1.u[0]); fma2(acc[2][3], ha3.u[1], qb1.u[0]);
            fma2(acc[3][0], ha0.u[1], qb1.u[1]); fma2(acc[3][1], ha1.u[1], qb1.u[1]);
            fma2(acc[3][2], ha2.u[1], qb1.u[1]); fma2(acc[3][3], ha3.u[1], qb1.u[1]);
            fma2(acc[4][0], ha0.u[1], qc1.u[0]); fma2(acc[4][1], ha1.u[1], qc1.u[0]);
            fma2(acc[4][2], ha2.u[1], qc1.u[0]); fma2(acc[4][3], ha3.u[1], qc1.u[0]);
            fma2(acc[5][0], ha0.u[1], qc1.u[1]); fma2(acc[5][1], ha1.u[1], qc1.u[1]);
            fma2(acc[5][2], ha2.u[1], qc1.u[1]); fma2(acc[5][3], ha3.u[1], qc1.u[1]);

            ha0 = hb0_; ha1 = hb1_; ha2 = hb2_; ha3 = hb3_;
        }

        // collapse k-parity lanes -> float gates gf[6][4]
        float gf[6][4];
#pragma unroll
        for (int j = 0; j < 6; j++)
#pragma unroll
            for (int b = 0; b < 4; b++) {
                float lo, hi; unpk2(acc[j][b], lo, hi);
                gf[j][b] = lo + hi;
            }

        // cross-kh float reduce. P0 = sS[0,3072); sG aliases [3072,6336).
        float* P0 = sS;
        float* sG = sS + 3072;
        if (kh == 2) {
#pragma unroll
            for (int j = 0; j < 6; j++)
#pragma unroll
                for (int b = 0; b < 4; b++) P0[r * 24 + j * 4 + b] = gf[j][b];
        }
        if (kh == 3) {
#pragma unroll
            for (int j = 0; j < 6; j++)
#pragma unroll
                for (int b = 0; b < 4; b++) sG[r * 24 + j * 4 + b] = gf[j][b];
        }
        __syncthreads();
        if (kh == 0) {
#pragma unroll
            for (int j = 0; j < 6; j++)
#pragma unroll
                for (int b = 0; b < 4; b++) gf[j][b] += P0[r * 24 + j * 4 + b];
        }
        if (kh == 1) {
#pragma unroll
            for (int j = 0; j < 6; j++)
#pragma unroll
                for (int b = 0; b < 4; b++) gf[j][b] += sG[r * 24 + j * 4 + b];
        }
        __syncthreads();
        if (kh == 1) {
#pragma unroll
            for (int j = 0; j < 6; j++)
#pragma unroll
                for (int b = 0; b < 4; b++) P0[r * 24 + j * 4 + b] = gf[j][b];
        }
        __syncthreads();
        if (kh == 0) {
#pragma unroll
            for (int j = 0; j < 6; j++)
#pragma unroll
                for (int b = 0; b < 4; b++) {
                    float v = gf[j][b] + P0[r * 24 + j * 4 + b];
                    sG[(c0 + j) * SGST + b0 + b] = v;
                }
        }
        __syncthreads();

        // epilogue compute (mapping A): gates+xg -> h_new into sHN
        float* sHN = sS + 6336;        // [16][SGST]
        {
            const float* xs = xgbase + (size_t)s * G_ * B_;
            F2 xz, xr, xh, hz, hr, hh, hn;
            xz.v = *(const float2*)(xs + (size_t)gu * B_ + eb);
            xr.v = *(const float2*)(xs + (size_t)(U_ + gu) * B_ + eb);
            xh.v = *(const float2*)(xs + (size_t)(2 * U_ + gu) * B_ + eb);
            hz.v = *(float2*)(sG + eu * SGST + eb);
            hr.v = *(float2*)(sG + (16 + eu) * SGST + eb);
            hh.v = *(float2*)(sG + (32 + eu) * SGST + eb);
#pragma unroll
            for (int e = 0; e < 2; e++) {
                float z  = sigf(xz.f[e] + hz.f[e]);
                float rr = sigf(xr.f[e] + hr.f[e]);
                float hc = tanhf(xh.f[e] + rr * hh.f[e]);
                hn.f[e]  = z * hpv.f[e] + (1.0f - z) * hc;
            }
            *(float2*)(sHN + eu * SGST + eb) = hn.v;
        }
        __syncthreads();

        // epilogue write (mapping B): transposed, coalesced into d_hT[dir][s]
        {
            F2 o;
            o.f[0] = sHN[up * SGST + b2];
            o.f[1] = sHN[(up + 1) * SGST + b2];
            __stcg((float2*)(&d_hT[dir][s][b2][u0 + up]), o.v);
        }

        // grid barrier (monotonic; 128 co-resident CTAs)
        __syncthreads();
        if (tid == 0) {
            __threadfence();
            unsigned target = nCTA * (unsigned)(s + 1);
            unsigned v = atomicAdd(&g_bar, 1u) + 1u;
            while (v < target) {
                __nanosleep(128);
                v = atomicAdd(&g_bar, 0u);
            }
            __threadfence();
        }
        __syncthreads();
    }
}

// ---------------- combine: out[b][t][u] = hT_f[t][b][u] + hT_b[T-1-t][b][u] ----------------
__global__ void k_comb(float* __restrict__ out) {
    int t = blockIdx.x, b = blockIdx.y;
    const float4* pf = (const float4*)(&d_hT[0][t][b][0]);
    const float4* pb = (const float4*)(&d_hT[1][T_ - 1 - t][b][0]);
    float4* po = (float4*)(out + ((size_t)b * T_ + t) * U_);
    int i = threadIdx.x;
    float4 a = pf[i], c = pb[i];
    float4 o; o.x = a.x + c.x; o.y = a.y + c.y; o.z = a.z + c.z; o.w = a.w + c.w;
    po[i] = o;
}

// ---------------- hidden concat: hidden[b][dir*U+u] = hT_dir[T-1][b][u] ----------------
__global__ void k_hid(float* __restrict__ out) {
    int dir = blockIdx.x, b = blockIdx.y;
    const float4* ph = (const float4*)(&d_hT[dir][T_ - 1][b][0]);
    float4* po = (float4*)(out + HID_OFF + (size_t)b * (2 * U_) + dir * U_);
    po[threadIdx.x] = ph[threadIdx.x];
}

extern "C" void kernel_launch(void* const* d_in, const int* in_sizes, int n_in,
                              void* d_out, int out_size) {
    const int*   tokens = (const int*)d_in[0];
    const float* emb    = (const float*)d_in[1];
    const float* Wf     = (const float*)d_in[2];
    const float* Uf     = (const float*)d_in[3];
    const float* bif    = (const float*)d_in[4];
    const float* bhf    = (const float*)d_in[5];
    const float* Wb     = (const float*)d_in[6];
    const float* Ub     = (const float*)d_in[7];
    const float* bib    = (const float*)d_in[8];
    const float* bhb    = (const float*)d_in[9];
    float* out = (float*)d_out;

    const int SMEM_REC = (48 * 1024 + 8192) * (int)sizeof(float);  // 229376 B
    cudaFuncSetAttribute(k_rec, cudaFuncAttributeMaxDynamicSharedMemorySize, SMEM_REC);

    k_init<<<64, 256>>>();
    k_embed<<<T_, 256>>>(tokens, emb);
    {
        dim3 g(64, T_, 2);
        k_gemm_in<<<g, 128>>>(Wf, Wb, bif, bib);
    }
    k_rec<<<128, 512, SMEM_REC>>>(Uf, Ub, bhf, bhb);
    {
        dim3 g(T_, B_);
        k_comb<<<g, 256>>>(out);
    }
    {
        dim3 g(2, B_);
        k_hid<<<g, 256>>>(out);
    }
    (void)in_sizes; (void)n_in; (void)out_size;
}

// round 13
// speedup vs baseline: 1.0461x; 1.0461x over previous
#include <cuda_runtime.h>
#include <cstdint>

#define B_ 64
#define T_ 128
#define E_ 512
#define U_ 1024
#define G_ 3072          // 3*U
#define SGST 68          // sG row stride (floats)
#define HID_OFF (B_*T_*U_)

typedef unsigned long long ull;

// ---------------- device scratch (static, allocation-free) ----------------
__device__ __align__(256) float d_XT[T_][E_][B_];       // emb(tokens), [t_orig][e][b]
__device__ __align__(256) float d_xg[2][T_][G_][B_];    // input projections per scan step
__device__ __align__(256) float d_outs[2][T_][U_][B_];  // per-dir hidden sequences (= h chain)
__device__ __align__(256) float d_h0[U_][B_];           // zero initial state (both dirs)
__device__ unsigned g_bar;                              // monotonic grid barrier

// ---------------- f32x2 helpers (Blackwell packed fp32) ----------------
__device__ __forceinline__ ull pk2(float v) {
    ull r; asm("mov.b64 %0, {%1, %1};" : "=l"(r) : "f"(v)); return r;
}
__device__ __forceinline__ ull mk2(float lo, float hi) {
    ull r; asm("mov.b64 %0, {%1, %2};" : "=l"(r) : "f"(lo), "f"(hi)); return r;
}
__device__ __forceinline__ void unpk2(ull v, float& lo, float& hi) {
    asm("mov.b64 {%0, %1}, %2;" : "=f"(lo), "=f"(hi) : "l"(v));
}
__device__ __forceinline__ void fma2(ull& d, ull a, ull b) {
    asm("fma.rn.f32x2 %0, %1, %2, %0;" : "+l"(d) : "l"(a), "l"(b));
}
__device__ __forceinline__ ull add2(ull a, ull b) {
    ull r; asm("add.rn.f32x2 %0, %1, %2;" : "=l"(r) : "l"(a), "l"(b)); return r;
}
__device__ __forceinline__ float sigf(float x) { return 1.0f / (1.0f + __expf(-x)); }

union F4 { float4 v; float f[4]; ull u[2]; };
union F2 { float2 v; float f[2]; };

// ---------------- init: zero h0, reset barrier ----------------
__global__ void k_init() {
    int n = U_ * B_;
    float* p = &d_h0[0][0];
    for (int i = blockIdx.x * blockDim.x + threadIdx.x; i < n; i += gridDim.x * blockDim.x)
        p[i] = 0.0f;
    if (blockIdx.x == 0 && threadIdx.x == 0) g_bar = 0u;
}

// ---------------- embedding gather (transposed store) ----------------
__global__ void k_embed(const int* __restrict__ tokens, const float* __restrict__ emb) {
    int t = blockIdx.x;
    int b = threadIdx.x & 63;
    int sub = threadIdx.x >> 6;
    int tok = tokens[b * T_ + t];
    const float* er = emb + (size_t)tok * E_;
    for (int e = sub; e < E_; e += 4)
        d_XT[t][e][b] = er[e];
}

// ---------------- input projection GEMM (unchanged, passing) ----------------
__global__ void __launch_bounds__(128) k_gemm_in(const float* __restrict__ Wf,
                                                 const float* __restrict__ Wb,
                                                 const float* __restrict__ bif,
                                                 const float* __restrict__ bib) {
    int gt = blockIdx.x, s = blockIdx.y, dir = blockIdx.z;
    int g0 = gt * 48;
    int torig = dir ? s : (T_ - 1 - s);
    const float* W  = dir ? Wb  : Wf;
    const float* bi = dir ? bib : bif;

    __shared__ __align__(16) float sW[64 * 48];
    __shared__ __align__(16) float sA[64 * 64];

    int tid = threadIdx.x;
    int kh = tid >> 6, r = tid & 63, cg = r >> 3, bg = r & 7;
    int b0 = bg << 3, c0 = cg * 6;

    ull acc[6][4];
#pragma unroll
    for (int j = 0; j < 6; j++) {
        ull init = kh ? 0ull : pk2(bi[g0 + c0 + j]);
#pragma unroll
        for (int p = 0; p < 4; p++) acc[j][p] = init;
    }

    for (int kc = 0; kc < E_ / 64; kc++) {
        __syncthreads();
        for (int idx = tid; idx < 64 * 48; idx += 128) {
            int kk = idx / 48, c = idx - kk * 48;
            sW[idx] = W[(size_t)(kc * 64 + kk) * G_ + g0 + c];
        }
        const float4* src = (const float4*)(&d_XT[torig][kc * 64][0]);
        float4* dst = (float4*)sA;
#pragma unroll
        for (int i = 0; i < 8; i++) dst[tid + i * 128] = src[tid + i * 128];
        __syncthreads();

        const float* hb  = sA + (kh * 32) * 64;
        const float* wb_ = sW + (kh * 32) * 48;
#pragma unroll 4
        for (int kk = 0; kk < 32; kk++) {
            ull hp[4];
#pragma unroll
            for (int p = 0; p < 4; p++) hp[p] = *(const ull*)(hb + kk * 64 + b0 + 2 * p);
#pragma unroll
            for (int j = 0; j < 6; j++) {
                ull us = pk2(wb_[kk * 48 + c0 + j]);
#pragma unroll
                for (int p = 0; p < 4; p++) fma2(acc[j][p], hp[p], us);
            }
        }
    }
    __syncthreads();
    ull* part = (ull*)sA;
    if (kh) {
#pragma unroll
        for (int j = 0; j < 6; j++)
#pragma unroll
            for (int p = 0; p < 4; p++) part[r * 24 + j * 4 + p] = acc[j][p];
    }
    __syncthreads();
    if (!kh) {
#pragma unroll
        for (int j = 0; j < 6; j++) {
#pragma unroll
            for (int q = 0; q < 2; q++) {
                F4 o;
                o.u[0] = add2(acc[j][2 * q + 0], part[r * 24 + j * 4 + 2 * q + 0]);
                o.u[1] = add2(acc[j][2 * q + 1], part[r * 24 + j * 4 + 2 * q + 1]);
                *(float4*)(&d_xg[dir][s][g0 + c0 + j][b0 + 4 * q]) = o.v;
            }
        }
    }
}

// ---------------- persistent recurrent kernel ----------------
// R13 = R11 + depth-3 software pipeline on h loads (three 2-row register
// buffers; load group g+3 while computing group g) to cover the 262-cyc L2
// latency that R11's single-group lookahead left exposed.
__global__ void __launch_bounds__(512, 1) k_rec(const float* __restrict__ Uf,
                                                const float* __restrict__ Ub,
                                                const float* __restrict__ bhf,
                                                const float* __restrict__ bhb) {
    extern __shared__ __align__(16) float smem[];
    float* sU = smem;                // U_*48 floats = 196608 B
    float* sH = smem + U_ * 48;      // 8192 floats = 32768 B scratch (partials / gates)

    int dir = blockIdx.x >> 6;
    int uc  = blockIdx.x & 63;
    int u0  = uc << 4;
    const float* Uw = dir ? Ub : Uf;
    const float* bh = dir ? bhb : bhf;
    int tid = threadIdx.x;
    unsigned nCTA = gridDim.x;

    // one-time: this CTA's Uw slice [1024 x 48] -> smem. col c: gate c>>4, u = u0+(c&15)
    for (int idx = tid; idx < U_ * 48; idx += 512) {
        int k = idx / 48, c = idx - k * 48;
        sU[idx] = Uw[(size_t)k * G_ + (c >> 4) * U_ + u0 + (c & 15)];
    }

    int kh = tid >> 7;                 // 0..3: contiguous quarter of k = [kh*256,(kh+1)*256)
    int r  = tid & 127;
    int cg = r & 7, bg = r >> 3;
    int c0 = cg * 6, b0 = bg * 4;

    // bias as column pairs (kh0 only)
    ull binit[3];
#pragma unroll
    for (int p = 0; p < 3; p++) {
        if (kh) { binit[p] = 0ull; continue; }
        int ca = c0 + 2 * p, cb = ca + 1;
        float lo = bh[(ca >> 4) * U_ + u0 + (ca & 15)];
        float hi = bh[(cb >> 4) * U_ + u0 + (cb & 15)];
        binit[p] = mk2(lo, hi);
    }

    // epilogue mapping: 512 tasks of (u, 2b); warp covers one u-row of 64 b
    int eu = tid >> 5;                 // 0..15
    int eb = (tid & 31) * 2;           // 0..62
    int gu = u0 + eu;
    const float* xgbase = &d_xg[dir][0][0][0];
    const float* ubB = sU + (size_t)(kh * 256) * 48 + c0;

    __syncthreads();                   // sU resident

    for (int s = 0; s < T_; s++) {
        const float* hprev = (s == 0) ? &d_h0[0][0] : &d_outs[dir][s - 1][0][0];
        const float* hb = hprev + (size_t)(kh * 256) * 64 + b0;

        // prefetch epilogue operands (consumed after the ~25k-cyc mainloop)
        const float* xs = xgbase + (size_t)s * G_ * B_;
        F2 xz, xr, xh, hpv;
        xz.v  = *(const float2*)(xs + (size_t)gu * B_ + eb);
        xr.v  = *(const float2*)(xs + (size_t)(U_ + gu) * B_ + eb);
        xh.v  = *(const float2*)(xs + (size_t)(2 * U_ + gu) * B_ + eb);
        hpv.v = __ldcg((const float2*)(hprev + (size_t)gu * B_ + eb));

        ull acc[3][4];
#pragma unroll
        for (int p = 0; p < 3; p++)
#pragma unroll
            for (int b = 0; b < 4; b++) acc[p][b] = binit[p];

        // ---- depth-3 pipelined mainloop: 128 groups of 2 k-rows ----
#define LOADG(x0, x1, g) do {                                        \
            (x0).v = __ldcg((const float4*)(hb + (size_t)(2*(g)) * 64));     \
            (x1).v = __ldcg((const float4*)(hb + (size_t)(2*(g)+1) * 64)); } while (0)
#define COMPG(x0, x1, g) do {                                        \
            const float* up0 = ubB + (size_t)(2*(g)) * 48;           \
            ull w0 = *(const ull*)(up0);                             \
            ull w1 = *(const ull*)(up0 + 2);                         \
            ull w2 = *(const ull*)(up0 + 4);                         \
            ull h0 = pk2((x0).f[0]), h1 = pk2((x0).f[1]),            \
                h2 = pk2((x0).f[2]), h3 = pk2((x0).f[3]);            \
            fma2(acc[0][0], h0, w0); fma2(acc[0][1], h1, w0);        \
            fma2(acc[0][2], h2, w0); fma2(acc[0][3], h3, w0);        \
            fma2(acc[1][0], h0, w1); fma2(acc[1][1], h1, w1);        \
            fma2(acc[1][2], h2, w1); fma2(acc[1][3], h3, w1);        \
            fma2(acc[2][0], h0, w2); fma2(acc[2][1], h1, w2);        \
            fma2(acc[2][2], h2, w2); fma2(acc[2][3], h3, w2);        \
            const float* up1 = up0 + 48;                             \
            ull v0 = *(const ull*)(up1);                             \
            ull v1 = *(const ull*)(up1 + 2);                         \
            ull v2 = *(const ull*)(up1 + 4);                         \
            ull g0_ = pk2((x1).f[0]), g1_ = pk2((x1).f[1]),          \
                g2_ = pk2((x1).f[2]), g3_ = pk2((x1).f[3]);          \
            fma2(acc[0][0], g0_, v0); fma2(acc[0][1], g1_, v0);      \
            fma2(acc[0][2], g2_, v0); fma2(acc[0][3], g3_, v0);      \
            fma2(acc[1][0], g0_, v1); fma2(acc[1][1], g1_, v1);      \
            fma2(acc[1][2], g2_, v1); fma2(acc[1][3], g3_, v1);      \
            fma2(acc[2][0], g0_, v2); fma2(acc[2][1], g1_, v2);      \
            fma2(acc[2][2], g2_, v2); fma2(acc[2][3], g3_, v2); } while (0)

        F4 a0, a1, b0_, b1_, c0_, c1_;
        LOADG(a0, a1, 0);
        LOADG(b0_, b1_, 1);
        LOADG(c0_, c1_, 2);
#pragma unroll 1
        for (int it = 0; it < 41; it++) {
            int g = 3 * it;
            COMPG(a0, a1, g);     LOADG(a0, a1, g + 3);
            COMPG(b0_, b1_, g + 1); LOADG(b0_, b1_, g + 4);
            COMPG(c0_, c1_, g + 2); LOADG(c0_, c1_, g + 5);
        }
        // groups 123..127 (buffers hold 123,124,125)
        COMPG(a0, a1, 123); LOADG(a0, a1, 126);
        COMPG(b0_, b1_, 124); LOADG(b0_, b1_, 127);
        COMPG(c0_, c1_, 125);
        COMPG(a0, a1, 126);
        COMPG(b0_, b1_, 127);
#undef LOADG
#undef COMPG

        // cross-kh reduce. P0 = ull[0,1536); P1 = ull[1536,3072).
        ull* part = (ull*)sH;
        if (kh == 2) {
#pragma unroll
            for (int p = 0; p < 3; p++)
#pragma unroll
                for (int b = 0; b < 4; b++) part[r * 12 + p * 4 + b] = acc[p][b];
        }
        if (kh == 3) {
#pragma unroll
            for (int p = 0; p < 3; p++)
#pragma unroll
                for (int b = 0; b < 4; b++) part[1536 + r * 12 + p * 4 + b] = acc[p][b];
        }
        __syncthreads();
        if (kh == 0) {
#pragma unroll
            for (int p = 0; p < 3; p++)
#pragma unroll
                for (int b = 0; b < 4; b++) acc[p][b] = add2(acc[p][b], part[r * 12 + p * 4 + b]);
        }
        if (kh == 1) {
#pragma unroll
            for (int p = 0; p < 3; p++)
#pragma unroll
                for (int b = 0; b < 4; b++) acc[p][b] = add2(acc[p][b], part[1536 + r * 12 + p * 4 + b]);
        }
        __syncthreads();
        if (kh == 1) {
#pragma unroll
            for (int p = 0; p < 3; p++)
#pragma unroll
                for (int b = 0; b < 4; b++) part[r * 12 + p * 4 + b] = acc[p][b];
        }
        __syncthreads();
        float* sG = sH + 3072;         // floats [3072, 6336) — P1 consumed by now
        if (kh == 0) {
#pragma unroll
            for (int p = 0; p < 3; p++) {
#pragma unroll
                for (int b = 0; b < 4; b++) {
                    ull v = add2(acc[p][b], part[r * 12 + p * 4 + b]);
                    float lo, hi; unpk2(v, lo, hi);
                    sG[(c0 + 2 * p) * SGST + b0 + b] = lo;
                    sG[(c0 + 2 * p + 1) * SGST + b0 + b] = hi;
                }
            }
        }
        __syncthreads();

        // epilogue: gates -> h_new, one (u, 2b) per thread; single store to d_outs[s]
        {
            F2 hz, hr, hh, hn;
            hz.v = *(float2*)(sG + eu * SGST + eb);
            hr.v = *(float2*)(sG + (16 + eu) * SGST + eb);
            hh.v = *(float2*)(sG + (32 + eu) * SGST + eb);
#pragma unroll
            for (int e = 0; e < 2; e++) {
                float z  = sigf(xz.f[e] + hz.f[e]);
                float rr = sigf(xr.f[e] + hr.f[e]);
                float hc = tanhf(xh.f[e] + rr * hh.f[e]);
                hn.f[e]  = z * hpv.f[e] + (1.0f - z) * hc;
            }
            __stcg((float2*)(&d_outs[dir][s][gu][eb]), hn.v);
        }

        // grid barrier (monotonic; 128 co-resident CTAs)
        __syncthreads();
        if (tid == 0) {
            __threadfence();
            unsigned target = nCTA * (unsigned)(s + 1);
            unsigned v = atomicAdd(&g_bar, 1u) + 1u;
            while (v < target) {
                __nanosleep(128);
                v = atomicAdd(&g_bar, 0u);
            }
            __threadfence();
        }
        __syncthreads();
    }
}

// ---------------- combine: out[b][t][u] = outs_f[t][u][b] + outs_b[T-1-t][u][b] ----------------
__global__ void k_comb(float* __restrict__ out) {
    __shared__ float sT[32][33];
    int t = blockIdx.x, u0 = blockIdx.y * 32, b0 = blockIdx.z * 32;
    int tx = threadIdx.x, ty = threadIdx.y;
#pragma unroll
    for (int i = 0; i < 4; i++) {
        int u = ty + i * 8;
        sT[u][tx] = d_outs[0][t][u0 + u][b0 + tx] + d_outs[1][T_ - 1 - t][u0 + u][b0 + tx];
    }
    __syncthreads();
#pragma unroll
    for (int i = 0; i < 4; i++) {
        int b = ty + i * 8;
        out[((size_t)(b0 + b) * T_ + t) * U_ + u0 + tx] = sT[tx][b];
    }
}

// ---------------- hidden concat ----------------
__global__ void k_hid(float* __restrict__ out) {
    __shared__ float sT[32][33];
    int u0 = blockIdx.x * 32, dir = blockIdx.y, b0 = blockIdx.z * 32;
    int tx = threadIdx.x, ty = threadIdx.y;
#pragma unroll
    for (int i = 0; i < 4; i++) {
        int u = ty + i * 8;
        sT[u][tx] = d_outs[dir][T_ - 1][u0 + u][b0 + tx];
    }
    __syncthreads();
#pragma unroll
    for (int i = 0; i < 4; i++) {
        int b = ty + i * 8;
        out[HID_OFF + (size_t)(b0 + b) * (2 * U_) + dir * U_ + u0 + tx] = sT[tx][b];
    }
}

extern "C" void kernel_launch(void* const* d_in, const int* in_sizes, int n_in,
                              void* d_out, int out_size) {
    const int*   tokens = (const int*)d_in[0];
    const float* emb    = (const float*)d_in[1];
    const float* Wf     = (const float*)d_in[2];
    const float* Uf     = (const float*)d_in[3];
    const float* bif    = (const float*)d_in[4];
    const float* bhf    = (const float*)d_in[5];
    const float* Wb     = (const float*)d_in[6];
    const float* Ub     = (const float*)d_in[7];
    const float* bib    = (const float*)d_in[8];
    const float* bhb    = (const float*)d_in[9];
    float* out = (float*)d_out;

    const int SMEM_REC = (U_ * 48 + 8192) * (int)sizeof(float);  // 229376 B
    cudaFuncSetAttribute(k_rec, cudaFuncAttributeMaxDynamicSharedMemorySize, SMEM_REC);

    k_init<<<64, 256>>>();
    k_embed<<<T_, 256>>>(tokens, emb);
    {
        dim3 g(64, T_, 2);
        k_gemm_in<<<g, 128>>>(Wf, Wb, bif, bib);
    }
    k_rec<<<128, 512, SMEM_REC>>>(Uf, Ub, bhf, bhb);
    {
        dim3 g(T_, U_ / 32, B_ / 32);
        k_comb<<<g, dim3(32, 8)>>>(out);
    }
    {
        dim3 g(U_ / 32, 2, B_ / 32);
        k_hid<<<g, dim3(32, 8)>>>(out);
    }
    (void)in_sizes; (void)n_in; (void)out_size;
}